// round 3
// baseline (speedup 1.0000x reference)
#include <cuda_runtime.h>

#define T_SEQ 4096
#define DM    1024
#define NH    16
#define HD    64

// Scratch (allocation-free: __device__ globals)
__device__ float g_qh[NH * T_SEQ * HD];   // [H][T][64]
__device__ float g_kh[NH * T_SEQ * HD];
__device__ float g_vh[NH * T_SEQ * HD];
__device__ float g_ao[T_SEQ * DM];        // attention output, [T][D]

// ---------------------------------------------------------------------------
// Tiled SGEMM: C[M,N] = X[M,K] @ W[N,K]^T + bias[N]
// BM=BN=64, BK=16, 256 threads, 4x4 per thread.
// MODE 0: scatter into head-major [h][m][d] layout (h = n>>6, d = n&63)
// MODE 1: plain row-major [m][n]
// ---------------------------------------------------------------------------
template <int MODE>
__device__ __forceinline__ void gemm_body(const float* __restrict__ X,
                                          const float* __restrict__ W,
                                          const float* __restrict__ bias,
                                          float* __restrict__ out) {
    __shared__ float As[16][68];   // [k][m], padded; row stride 68 keeps 16B align
    __shared__ float Bs[16][68];   // [k][n]
    const int tid = threadIdx.x;
    const int tx = tid & 15, ty = tid >> 4;
    const int bm = blockIdx.y * 64, bn = blockIdx.x * 64;
    const int lr = tid >> 2;            // load row within tile (0..63)
    const int lk = (tid & 3) << 2;      // k offset within tile (0,4,8,12)
    const float* Xp = X + (size_t)(bm + lr) * DM + lk;
    const float* Wp = W + (size_t)(bn + lr) * DM + lk;

    float acc[4][4] = {};
    for (int k0 = 0; k0 < DM; k0 += 16) {
        float4 a = *(const float4*)(Xp + k0);
        float4 b = *(const float4*)(Wp + k0);
        As[lk + 0][lr] = a.x; As[lk + 1][lr] = a.y;
        As[lk + 2][lr] = a.z; As[lk + 3][lr] = a.w;
        Bs[lk + 0][lr] = b.x; Bs[lk + 1][lr] = b.y;
        Bs[lk + 2][lr] = b.z; Bs[lk + 3][lr] = b.w;
        __syncthreads();
#pragma unroll
        for (int kk = 0; kk < 16; kk++) {
            float4 av = *(const float4*)&As[kk][ty << 2];
            float4 bv = *(const float4*)&Bs[kk][tx << 2];
            float aa[4] = {av.x, av.y, av.z, av.w};
            float bb[4] = {bv.x, bv.y, bv.z, bv.w};
#pragma unroll
            for (int i = 0; i < 4; i++)
#pragma unroll
                for (int j = 0; j < 4; j++)
                    acc[i][j] = fmaf(aa[i], bb[j], acc[i][j]);
        }
        __syncthreads();
    }

    float4 bv4 = *(const float4*)(bias + bn + (tx << 2));
    float bb[4] = {bv4.x, bv4.y, bv4.z, bv4.w};
#pragma unroll
    for (int i = 0; i < 4; i++) {
        int m = bm + (ty << 2) + i;
        float4 v;
        v.x = acc[i][0] + bb[0];
        v.y = acc[i][1] + bb[1];
        v.z = acc[i][2] + bb[2];
        v.w = acc[i][3] + bb[3];
        if (MODE == 0) {
            int h = bn >> 6;                 // bn is a multiple of 64; head id
            int d = (tx << 2);               // (bn & 63) == 0
            *(float4*)(out + ((size_t)(h * T_SEQ + m)) * HD + d) = v;
        } else {
            *(float4*)(out + (size_t)m * DM + bn + (tx << 2)) = v;
        }
    }
}

__global__ void gemm_proj(const float* __restrict__ X,
                          const float* __restrict__ W,
                          const float* __restrict__ bias, int which) {
    float* out = (which == 0) ? g_qh : (which == 1) ? g_kh : g_vh;
    gemm_body<0>(X, W, bias, out);
}

__global__ void gemm_out_k(const float* __restrict__ W,
                           const float* __restrict__ bias,
                           float* __restrict__ out) {
    gemm_body<1>(g_ao, W, bias, out);
}

// ---------------------------------------------------------------------------
// Flash attention (fp32, causal). One block per (64-query tile, head).
// Online softmax; diagonal tile masked elementwise; masked exp underflows to 0
// exactly like the reference's -10000 bias, so results match bitwise-in-effect.
// Smem: Qs/Ks [d][r] transposed, Vs [c][d], Ps [c][r]  => 4 * 64*68*4 = 69632 B
// ---------------------------------------------------------------------------
#define ATT_SMEM (4 * 64 * 68 * 4)

__global__ void flash_attn_kernel() {
    extern __shared__ float sm[];
    float* Qs = sm;                // Qs[d*68 + r]
    float* Ks = Qs + 64 * 68;      // Ks[d*68 + c]
    float* Vs = Ks + 64 * 68;      // Vs[c*68 + d]
    float* Ps = Vs + 64 * 68;      // Ps[c*68 + r]

    const int tid = threadIdx.x;
    const int tx = tid & 15, ty = tid >> 4;
    const int qt = blockIdx.x, h = blockIdx.y;
    const int q0 = qt * 64;

    const float* Qg = g_qh + ((size_t)h * T_SEQ + q0) * HD;
    {   // load Q transposed: Qs[d][r]
        int r = tid >> 2, dv = (tid & 3) << 2;
#pragma unroll
        for (int it = 0; it < 4; it++) {
            int d = dv + it * 16;
            float4 v = *(const float4*)(Qg + r * HD + d);
            Qs[(d + 0) * 68 + r] = v.x; Qs[(d + 1) * 68 + r] = v.y;
            Qs[(d + 2) * 68 + r] = v.z; Qs[(d + 3) * 68 + r] = v.w;
        }
    }

    float O[4][4] = {};
    float mrow[4] = {-1e30f, -1e30f, -1e30f, -1e30f};
    float lrow[4] = {0.f, 0.f, 0.f, 0.f};

    for (int kt = 0; kt <= qt; kt++) {
        __syncthreads();   // prev iteration done reading Ks/Vs/Ps (and Q store visible)
        const float* Kg = g_kh + ((size_t)h * T_SEQ + kt * 64) * HD;
        const float* Vg = g_vh + ((size_t)h * T_SEQ + kt * 64) * HD;
        {
            int r = tid >> 2, dv = (tid & 3) << 2;
#pragma unroll
            for (int it = 0; it < 4; it++) {
                int d = dv + it * 16;
                float4 kv = *(const float4*)(Kg + r * HD + d);
                Ks[(d + 0) * 68 + r] = kv.x; Ks[(d + 1) * 68 + r] = kv.y;
                Ks[(d + 2) * 68 + r] = kv.z; Ks[(d + 3) * 68 + r] = kv.w;
                float4 vv = *(const float4*)(Vg + r * HD + d);
                *(float4*)(Vs + r * 68 + d) = vv;
            }
        }
        __syncthreads();

        // S = Q @ K^T  (64x64, each thread 4x4)
        float s[4][4] = {};
#pragma unroll 8
        for (int d = 0; d < 64; d++) {
            float4 qv = *(const float4*)&Qs[d * 68 + (ty << 2)];
            float4 kv = *(const float4*)&Ks[d * 68 + (tx << 2)];
            float qa[4] = {qv.x, qv.y, qv.z, qv.w};
            float ka[4] = {kv.x, kv.y, kv.z, kv.w};
#pragma unroll
            for (int i = 0; i < 4; i++)
#pragma unroll
                for (int j = 0; j < 4; j++)
                    s[i][j] = fmaf(qa[i], ka[j], s[i][j]);
        }

        const float scale = 0.125f;   // 1/sqrt(64)
        if (kt == qt) {
#pragma unroll
            for (int i = 0; i < 4; i++)
#pragma unroll
                for (int j = 0; j < 4; j++) {
                    int qi = (ty << 2) + i, kj = (tx << 2) + j;
                    s[i][j] = (kj <= qi) ? s[i][j] * scale : -1e30f;
                }
        } else {
#pragma unroll
            for (int i = 0; i < 4; i++)
#pragma unroll
                for (int j = 0; j < 4; j++) s[i][j] *= scale;
        }

        // online softmax; row i spans 16 consecutive lanes (same ty), width-16 shfl
#pragma unroll
        for (int i = 0; i < 4; i++) {
            float rm = fmaxf(fmaxf(s[i][0], s[i][1]), fmaxf(s[i][2], s[i][3]));
#pragma unroll
            for (int off = 8; off >= 1; off >>= 1)
                rm = fmaxf(rm, __shfl_xor_sync(0xffffffffu, rm, off, 16));
            float mnew = fmaxf(mrow[i], rm);
            float alpha = __expf(mrow[i] - mnew);
            mrow[i] = mnew;
            float rs = 0.f;
#pragma unroll
            for (int j = 0; j < 4; j++) {
                s[i][j] = __expf(s[i][j] - mnew);
                rs += s[i][j];
            }
#pragma unroll
            for (int off = 8; off >= 1; off >>= 1)
                rs += __shfl_xor_sync(0xffffffffu, rs, off, 16);
            lrow[i] = lrow[i] * alpha + rs;
#pragma unroll
            for (int j = 0; j < 4; j++) O[i][j] *= alpha;
        }

        // P -> shared, transposed: Ps[c][r]
#pragma unroll
        for (int i = 0; i < 4; i++)
#pragma unroll
            for (int j = 0; j < 4; j++)
                Ps[((tx << 2) + j) * 68 + (ty << 2) + i] = s[i][j];
        __syncthreads();

        // O += P @ V
#pragma unroll 8
        for (int c = 0; c < 64; c++) {
            float4 pv = *(const float4*)&Ps[c * 68 + (ty << 2)];
            float4 vv = *(const float4*)&Vs[c * 68 + (tx << 2)];
            float pa[4] = {pv.x, pv.y, pv.z, pv.w};
            float va[4] = {vv.x, vv.y, vv.z, vv.w};
#pragma unroll
            for (int i = 0; i < 4; i++)
#pragma unroll
                for (int j = 0; j < 4; j++)
                    O[i][j] = fmaf(pa[i], va[j], O[i][j]);
        }
    }

    // epilogue: O / l  -> g_ao[t][h*64 + d]
#pragma unroll
    for (int i = 0; i < 4; i++) {
        float inv = 1.0f / lrow[i];
        int row = q0 + (ty << 2) + i;
        float4 v;
        v.x = O[i][0] * inv; v.y = O[i][1] * inv;
        v.z = O[i][2] * inv; v.w = O[i][3] * inv;
        *(float4*)(g_ao + (size_t)row * DM + h * HD + (tx << 2)) = v;
    }
}

// ---------------------------------------------------------------------------
extern "C" void kernel_launch(void* const* d_in, const int* in_sizes, int n_in,
                              void* d_out, int out_size) {
    const float* q   = (const float*)d_in[0];
    const float* k   = (const float*)d_in[1];
    const float* v   = (const float*)d_in[2];
    // d_in[3] = causal mask (bool) — implied by causal structure, unused
    const float* w_q = (const float*)d_in[4];
    const float* b_q = (const float*)d_in[5];
    const float* w_k = (const float*)d_in[6];
    const float* b_k = (const float*)d_in[7];
    const float* w_v = (const float*)d_in[8];
    const float* b_v = (const float*)d_in[9];
    const float* w_o = (const float*)d_in[10];
    const float* b_o = (const float*)d_in[11];
    float* out = (float*)d_out;

    cudaFuncSetAttribute(flash_attn_kernel,
                         cudaFuncAttributeMaxDynamicSharedMemorySize, ATT_SMEM);

    dim3 gp(DM / 64, T_SEQ / 64);
    gemm_proj<<<gp, 256>>>(q, w_q, b_q, 0);
    gemm_proj<<<gp, 256>>>(k, w_k, b_k, 1);
    gemm_proj<<<gp, 256>>>(v, w_v, b_v, 2);
    flash_attn_kernel<<<dim3(T_SEQ / 64, NH), 256, ATT_SMEM>>>();
    gemm_out_k<<<gp, 256>>>(w_o, b_o, out);
}

// round 5
// speedup vs baseline: 1.3382x; 1.3382x over previous
#include <cuda_runtime.h>
#include <cuda_bf16.h>
#include <cstdint>

#define T_SEQ 4096
#define DM    1024
#define NH    16
#define HD    64

// Scratch (allocation-free: __device__ globals)
__device__ float g_qh[NH * T_SEQ * HD];   // [H][T][64]
__device__ float g_kh[NH * T_SEQ * HD];
__device__ float g_vh[NH * T_SEQ * HD];
__device__ float g_ao[T_SEQ * DM];        // attention output, [T][D]

// ===========================================================================
// Helpers
// ===========================================================================
__device__ __forceinline__ uint32_t smem_to_u32(const void* p) {
    uint32_t a;
    asm("{ .reg .u64 t; cvta.to.shared.u64 t, %1; cvt.u32.u64 %0, t; }"
        : "=r"(a) : "l"(p));
    return a;
}

__device__ __forceinline__ void ldmatrix_x4(uint32_t* r, uint32_t addr) {
    asm volatile("ldmatrix.sync.aligned.m8n8.x4.shared.b16 {%0,%1,%2,%3}, [%4];"
                 : "=r"(r[0]), "=r"(r[1]), "=r"(r[2]), "=r"(r[3]) : "r"(addr));
}

__device__ __forceinline__ void mma16816(float* c, const uint32_t* a,
                                         uint32_t b0, uint32_t b1) {
    asm volatile(
        "mma.sync.aligned.m16n8k16.row.col.f32.bf16.bf16.f32 "
        "{%0,%1,%2,%3}, {%4,%5,%6,%7}, {%8,%9}, {%0,%1,%2,%3};"
        : "+f"(c[0]), "+f"(c[1]), "+f"(c[2]), "+f"(c[3])
        : "r"(a[0]), "r"(a[1]), "r"(a[2]), "r"(a[3]), "r"(b0), "r"(b1));
}

// fp32 -> (hi, lo) bf16 split; lo = rn(x - bf16(x)).  Dropped lo*lo term is
// O(2^-18) relative -> final rel err ~1e-5.
__device__ __forceinline__ void split4(float4 v, uint32_t& h0, uint32_t& h1,
                                       uint32_t& l0, uint32_t& l1) {
    __nv_bfloat162 hA = __floats2bfloat162_rn(v.x, v.y);
    __nv_bfloat162 hB = __floats2bfloat162_rn(v.z, v.w);
    __nv_bfloat162 lA = __floats2bfloat162_rn(v.x - __bfloat162float(hA.x),
                                              v.y - __bfloat162float(hA.y));
    __nv_bfloat162 lB = __floats2bfloat162_rn(v.z - __bfloat162float(hB.x),
                                              v.w - __bfloat162float(hB.y));
    h0 = *(uint32_t*)&hA; h1 = *(uint32_t*)&hB;
    l0 = *(uint32_t*)&lA; l1 = *(uint32_t*)&lB;
}

// ===========================================================================
// HMMA GEMM: C[M, N=1024] = X[M, K=1024] @ W[N, K]^T + bias[N]
// CTA 128x128, 8 warps (4m x 2n), warp tile 32x64, K chunk 32.
// 3-term bf16 split for fp32-grade accuracy. Smem stride 40 bf16 (80 B) keeps
// ldmatrix conflict-free (8 rows x 80B -> 8 distinct bank groups).
// MODE 0: scatter to head-major [h][t][64]; MODE 1: row-major [m][n].
// ===========================================================================
template <int MODE>
__device__ __forceinline__ void gemm_mma_body(const float* __restrict__ X,
                                              const float* __restrict__ W,
                                              const float* __restrict__ bias,
                                              float* __restrict__ out) {
    __shared__ __nv_bfloat16 sAhi[128 * 40];
    __shared__ __nv_bfloat16 sAlo[128 * 40];
    __shared__ __nv_bfloat16 sBhi[128 * 40];
    __shared__ __nv_bfloat16 sBlo[128 * 40];

    const int tid = threadIdx.x;
    const int w = tid >> 5, lane = tid & 31;
    const int wm = w & 3, wn = w >> 2;          // 4 x 2 warp grid
    const int bm = blockIdx.y * 128, bn = blockIdx.x * 128;

    const uint32_t uAhi = smem_to_u32(sAhi), uAlo = smem_to_u32(sAlo);
    const uint32_t uBhi = smem_to_u32(sBhi), uBlo = smem_to_u32(sBlo);

    // ldmatrix source lane mapping (canonical 16x16 idiom):
    // lane -> row (l & 15), k-halve byte offset (l >> 4) * 16
    const uint32_t mrow = lane & 15;
    const uint32_t mkb = (lane >> 4) * 16;

    // global load mapping: 1024 float4 per matrix chunk; thread covers 4
    const int grow = tid >> 3;        // rows 0..31 (+32 per i)
    const int gc4 = tid & 7;          // float4 within 32-float row
    const float* Xp = X + (size_t)(bm + grow) * DM + gc4 * 4;
    const float* Wp = W + (size_t)(bn + grow) * DM + gc4 * 4;

    float c[2][8][4] = {};

    for (int k0 = 0; k0 < DM; k0 += 32) {
        float4 av[4], bv[4];
#pragma unroll
        for (int i = 0; i < 4; i++) {
            av[i] = *(const float4*)(Xp + k0 + (size_t)i * 32 * DM);
            bv[i] = *(const float4*)(Wp + k0 + (size_t)i * 32 * DM);
        }
        __syncthreads();   // previous iteration's compute done
#pragma unroll
        for (int i = 0; i < 4; i++) {
            uint32_t byte = (uint32_t)(grow + 32 * i) * 80u + (uint32_t)gc4 * 8u;
            uint32_t h0, h1, l0, l1;
            split4(av[i], h0, h1, l0, l1);
            asm volatile("st.shared.v2.b32 [%0], {%1,%2};" :: "r"(uAhi + byte), "r"(h0), "r"(h1) : "memory");
            asm volatile("st.shared.v2.b32 [%0], {%1,%2};" :: "r"(uAlo + byte), "r"(l0), "r"(l1) : "memory");
            split4(bv[i], h0, h1, l0, l1);
            asm volatile("st.shared.v2.b32 [%0], {%1,%2};" :: "r"(uBhi + byte), "r"(h0), "r"(h1) : "memory");
            asm volatile("st.shared.v2.b32 [%0], {%1,%2};" :: "r"(uBlo + byte), "r"(l0), "r"(l1) : "memory");
        }
        __syncthreads();

#pragma unroll
        for (int ks = 0; ks < 2; ks++) {
            const uint32_t kbyte = (uint32_t)ks * 32u + mkb;
            uint32_t ah[2][4], al[2][4];
#pragma unroll
            for (int mt = 0; mt < 2; mt++) {
                uint32_t off = (uint32_t)(wm * 32 + mt * 16 + mrow) * 80u + kbyte;
                ldmatrix_x4(ah[mt], uAhi + off);
                ldmatrix_x4(al[mt], uAlo + off);
            }
#pragma unroll
            for (int np = 0; np < 4; np++) {
                uint32_t bh[4], bl[4];
                uint32_t off = (uint32_t)(wn * 64 + np * 16 + mrow) * 80u + kbyte;
                ldmatrix_x4(bh, uBhi + off);
                ldmatrix_x4(bl, uBlo + off);
#pragma unroll
                for (int mt = 0; mt < 2; mt++) {
                    float* c0 = c[mt][2 * np + 0];
                    float* c1 = c[mt][2 * np + 1];
                    mma16816(c0, ah[mt], bh[0], bh[2]);   // hi*hi
                    mma16816(c1, ah[mt], bh[1], bh[3]);
                    mma16816(c0, ah[mt], bl[0], bl[2]);   // hi*lo
                    mma16816(c1, ah[mt], bl[1], bl[3]);
                    mma16816(c0, al[mt], bh[0], bh[2]);   // lo*hi
                    mma16816(c1, al[mt], bh[1], bh[3]);
                }
            }
        }
    }

    // Epilogue: fragment layout c = {(g,2tg),(g,2tg+1),(g+8,2tg),(g+8,2tg+1)}
    const int g = lane >> 2, tg = lane & 3;
#pragma unroll
    for (int mt = 0; mt < 2; mt++) {
#pragma unroll
        for (int j = 0; j < 8; j++) {
            int col = bn + wn * 64 + j * 8 + tg * 2;
            float bb0 = __ldg(bias + col), bb1 = __ldg(bias + col + 1);
            int r0 = bm + wm * 32 + mt * 16 + g;
            float2 v0 = {c[mt][j][0] + bb0, c[mt][j][1] + bb1};
            float2 v1 = {c[mt][j][2] + bb0, c[mt][j][3] + bb1};
            if (MODE == 0) {
                size_t basep = ((size_t)((col >> 6) * T_SEQ)) * HD + (col & 63);
                *(float2*)(out + basep + (size_t)r0 * HD) = v0;
                *(float2*)(out + basep + (size_t)(r0 + 8) * HD) = v1;
            } else {
                *(float2*)(out + (size_t)r0 * DM + col) = v0;
                *(float2*)(out + (size_t)(r0 + 8) * DM + col) = v1;
            }
        }
    }
}

__global__ void __launch_bounds__(256, 2) gemm_mma_proj(const float* __restrict__ X,
                                                        const float* __restrict__ W,
                                                        const float* __restrict__ bias,
                                                        int which) {
    float* out = (which == 0) ? g_qh : (which == 1) ? g_kh : g_vh;
    gemm_mma_body<0>(X, W, bias, out);
}

__global__ void __launch_bounds__(256, 2) gemm_mma_out(const float* __restrict__ W,
                                                       const float* __restrict__ bias,
                                                       float* __restrict__ out) {
    gemm_mma_body<1>(g_ao, W, bias, out);
}

// ---------------------------------------------------------------------------
// Flash attention (fp32, causal) — unchanged known-good baseline (R5 target).
// ---------------------------------------------------------------------------
#define ATT_SMEM (4 * 64 * 68 * 4)

__global__ void flash_attn_kernel() {
    extern __shared__ float sm[];
    float* Qs = sm;                // Qs[d*68 + r]
    float* Ks = Qs + 64 * 68;      // Ks[d*68 + c]
    float* Vs = Ks + 64 * 68;      // Vs[c*68 + d]
    float* Ps = Vs + 64 * 68;      // Ps[c*68 + r]

    const int tid = threadIdx.x;
    const int tx = tid & 15, ty = tid >> 4;
    const int qt = blockIdx.x, h = blockIdx.y;
    const int q0 = qt * 64;

    const float* Qg = g_qh + ((size_t)h * T_SEQ + q0) * HD;
    {
        int r = tid >> 2, dv = (tid & 3) << 2;
#pragma unroll
        for (int it = 0; it < 4; it++) {
            int d = dv + it * 16;
            float4 v = *(const float4*)(Qg + r * HD + d);
            Qs[(d + 0) * 68 + r] = v.x; Qs[(d + 1) * 68 + r] = v.y;
            Qs[(d + 2) * 68 + r] = v.z; Qs[(d + 3) * 68 + r] = v.w;
        }
    }

    float O[4][4] = {};
    float mrow[4] = {-1e30f, -1e30f, -1e30f, -1e30f};
    float lrow[4] = {0.f, 0.f, 0.f, 0.f};

    for (int kt = 0; kt <= qt; kt++) {
        __syncthreads();
        const float* Kg = g_kh + ((size_t)h * T_SEQ + kt * 64) * HD;
        const float* Vg = g_vh + ((size_t)h * T_SEQ + kt * 64) * HD;
        {
            int r = tid >> 2, dv = (tid & 3) << 2;
#pragma unroll
            for (int it = 0; it < 4; it++) {
                int d = dv + it * 16;
                float4 kv = *(const float4*)(Kg + r * HD + d);
                Ks[(d + 0) * 68 + r] = kv.x; Ks[(d + 1) * 68 + r] = kv.y;
                Ks[(d + 2) * 68 + r] = kv.z; Ks[(d + 3) * 68 + r] = kv.w;
                float4 vv = *(const float4*)(Vg + r * HD + d);
                *(float4*)(Vs + r * 68 + d) = vv;
            }
        }
        __syncthreads();

        float s[4][4] = {};
#pragma unroll 8
        for (int d = 0; d < 64; d++) {
            float4 qv = *(const float4*)&Qs[d * 68 + (ty << 2)];
            float4 kv = *(const float4*)&Ks[d * 68 + (tx << 2)];
            float qa[4] = {qv.x, qv.y, qv.z, qv.w};
            float ka[4] = {kv.x, kv.y, kv.z, kv.w};
#pragma unroll
            for (int i = 0; i < 4; i++)
#pragma unroll
                for (int j = 0; j < 4; j++)
                    s[i][j] = fmaf(qa[i], ka[j], s[i][j]);
        }

        const float scale = 0.125f;
        if (kt == qt) {
#pragma unroll
            for (int i = 0; i < 4; i++)
#pragma unroll
                for (int j = 0; j < 4; j++) {
                    int qi = (ty << 2) + i, kj = (tx << 2) + j;
                    s[i][j] = (kj <= qi) ? s[i][j] * scale : -1e30f;
                }
        } else {
#pragma unroll
            for (int i = 0; i < 4; i++)
#pragma unroll
                for (int j = 0; j < 4; j++) s[i][j] *= scale;
        }

#pragma unroll
        for (int i = 0; i < 4; i++) {
            float rm = fmaxf(fmaxf(s[i][0], s[i][1]), fmaxf(s[i][2], s[i][3]));
#pragma unroll
            for (int off = 8; off >= 1; off >>= 1)
                rm = fmaxf(rm, __shfl_xor_sync(0xffffffffu, rm, off, 16));
            float mnew = fmaxf(mrow[i], rm);
            float alpha = __expf(mrow[i] - mnew);
            mrow[i] = mnew;
            float rs = 0.f;
#pragma unroll
            for (int j = 0; j < 4; j++) {
                s[i][j] = __expf(s[i][j] - mnew);
                rs += s[i][j];
            }
#pragma unroll
            for (int off = 8; off >= 1; off >>= 1)
                rs += __shfl_xor_sync(0xffffffffu, rs, off, 16);
            lrow[i] = lrow[i] * alpha + rs;
#pragma unroll
            for (int j = 0; j < 4; j++) O[i][j] *= alpha;
        }

#pragma unroll
        for (int i = 0; i < 4; i++)
#pragma unroll
            for (int j = 0; j < 4; j++)
                Ps[((tx << 2) + j) * 68 + (ty << 2) + i] = s[i][j];
        __syncthreads();

#pragma unroll 8
        for (int c = 0; c < 64; c++) {
            float4 pv = *(const float4*)&Ps[c * 68 + (ty << 2)];
            float4 vv = *(const float4*)&Vs[c * 68 + (tx << 2)];
            float pa[4] = {pv.x, pv.y, pv.z, pv.w};
            float va[4] = {vv.x, vv.y, vv.z, vv.w};
#pragma unroll
            for (int i = 0; i < 4; i++)
#pragma unroll
                for (int j = 0; j < 4; j++)
                    O[i][j] = fmaf(pa[i], va[j], O[i][j]);
        }
    }

#pragma unroll
    for (int i = 0; i < 4; i++) {
        float inv = 1.0f / lrow[i];
        int row = q0 + (ty << 2) + i;
        float4 v;
        v.x = O[i][0] * inv; v.y = O[i][1] * inv;
        v.z = O[i][2] * inv; v.w = O[i][3] * inv;
        *(float4*)(g_ao + (size_t)row * DM + h * HD + (tx << 2)) = v;
    }
}

// ---------------------------------------------------------------------------
extern "C" void kernel_launch(void* const* d_in, const int* in_sizes, int n_in,
                              void* d_out, int out_size) {
    const float* q   = (const float*)d_in[0];
    const float* k   = (const float*)d_in[1];
    const float* v   = (const float*)d_in[2];
    // d_in[3] = causal mask (bool) — implied by causal structure, unused
    const float* w_q = (const float*)d_in[4];
    const float* b_q = (const float*)d_in[5];
    const float* w_k = (const float*)d_in[6];
    const float* b_k = (const float*)d_in[7];
    const float* w_v = (const float*)d_in[8];
    const float* b_v = (const float*)d_in[9];
    const float* w_o = (const float*)d_in[10];
    const float* b_o = (const float*)d_in[11];
    float* out = (float*)d_out;

    cudaFuncSetAttribute(flash_attn_kernel, cudaFuncAttributeMaxDynamicSharedMemorySize, ATT_SMEM);

    dim3 gg(DM / 128, T_SEQ / 128);   // (8, 32)
    gemm_mma_proj<<<gg, 256>>>(q, w_q, b_q, 0);
    gemm_mma_proj<<<gg, 256>>>(k, w_k, b_k, 1);
    gemm_mma_proj<<<gg, 256>>>(v, w_v, b_v, 2);
    flash_attn_kernel<<<dim3(T_SEQ / 64, NH), 256, ATT_SMEM>>>();
    gemm_mma_out<<<gg, 256>>>(w_o, b_o, out);
}

// round 7
// speedup vs baseline: 2.8474x; 2.1278x over previous
#include <cuda_runtime.h>
#include <cuda_bf16.h>
#include <cstdint>

#define T_SEQ 4096
#define DM    1024
#define NH    16
#define HD    64

// Scratch (allocation-free: __device__ globals)
__device__ float g_qh[NH * T_SEQ * HD];   // [H][T][64]
__device__ float g_kh[NH * T_SEQ * HD];
__device__ float g_vh[NH * T_SEQ * HD];
__device__ float g_ao[T_SEQ * DM];        // attention output, [T][D]

// ===========================================================================
// Helpers
// ===========================================================================
__device__ __forceinline__ uint32_t smem_to_u32(const void* p) {
    uint32_t a;
    asm("{ .reg .u64 t; cvta.to.shared.u64 t, %1; cvt.u32.u64 %0, t; }"
        : "=r"(a) : "l"(p));
    return a;
}

__device__ __forceinline__ void ldmatrix_x4(uint32_t* r, uint32_t addr) {
    asm volatile("ldmatrix.sync.aligned.m8n8.x4.shared.b16 {%0,%1,%2,%3}, [%4];"
                 : "=r"(r[0]), "=r"(r[1]), "=r"(r[2]), "=r"(r[3]) : "r"(addr));
}

__device__ __forceinline__ void ldmatrix_x4_trans(uint32_t* r, uint32_t addr) {
    asm volatile("ldmatrix.sync.aligned.m8n8.x4.trans.shared.b16 {%0,%1,%2,%3}, [%4];"
                 : "=r"(r[0]), "=r"(r[1]), "=r"(r[2]), "=r"(r[3]) : "r"(addr));
}

__device__ __forceinline__ void mma16816(float* c, const uint32_t* a,
                                         uint32_t b0, uint32_t b1) {
    asm volatile(
        "mma.sync.aligned.m16n8k16.row.col.f32.bf16.bf16.f32 "
        "{%0,%1,%2,%3}, {%4,%5,%6,%7}, {%8,%9}, {%0,%1,%2,%3};"
        : "+f"(c[0]), "+f"(c[1]), "+f"(c[2]), "+f"(c[3])
        : "r"(a[0]), "r"(a[1]), "r"(a[2]), "r"(a[3]), "r"(b0), "r"(b1));
}

__device__ __forceinline__ uint32_t packbf2(float x, float y) {
    __nv_bfloat162 h = __floats2bfloat162_rn(x, y);
    return *(uint32_t*)&h;
}

// fp32 -> (hi, lo) bf16 split; lo = rn(x - bf16(x)).
__device__ __forceinline__ void split4(float4 v, uint32_t& h0, uint32_t& h1,
                                       uint32_t& l0, uint32_t& l1) {
    __nv_bfloat162 hA = __floats2bfloat162_rn(v.x, v.y);
    __nv_bfloat162 hB = __floats2bfloat162_rn(v.z, v.w);
    __nv_bfloat162 lA = __floats2bfloat162_rn(v.x - __bfloat162float(hA.x),
                                              v.y - __bfloat162float(hA.y));
    __nv_bfloat162 lB = __floats2bfloat162_rn(v.z - __bfloat162float(hB.x),
                                              v.w - __bfloat162float(hB.y));
    h0 = *(uint32_t*)&hA; h1 = *(uint32_t*)&hB;
    l0 = *(uint32_t*)&lA; l1 = *(uint32_t*)&lB;
}

// ===========================================================================
// HMMA GEMM: C[M, N=1024] = X[M, K=1024] @ W[N, K]^T + bias[N]  (R4, WIN)
// CTA 128x128, 8 warps (4m x 2n), warp tile 32x64, K chunk 32, stride 80 B.
// ===========================================================================
template <int MODE>
__device__ __forceinline__ void gemm_mma_body(const float* __restrict__ X,
                                              const float* __restrict__ W,
                                              const float* __restrict__ bias,
                                              float* __restrict__ out) {
    __shared__ __nv_bfloat16 sAhi[128 * 40];
    __shared__ __nv_bfloat16 sAlo[128 * 40];
    __shared__ __nv_bfloat16 sBhi[128 * 40];
    __shared__ __nv_bfloat16 sBlo[128 * 40];

    const int tid = threadIdx.x;
    const int w = tid >> 5, lane = tid & 31;
    const int wm = w & 3, wn = w >> 2;
    const int bm = blockIdx.y * 128, bn = blockIdx.x * 128;

    const uint32_t uAhi = smem_to_u32(sAhi), uAlo = smem_to_u32(sAlo);
    const uint32_t uBhi = smem_to_u32(sBhi), uBlo = smem_to_u32(sBlo);

    const uint32_t mrow = lane & 15;
    const uint32_t mkb = (lane >> 4) * 16;

    const int grow = tid >> 3;
    const int gc4 = tid & 7;
    const float* Xp = X + (size_t)(bm + grow) * DM + gc4 * 4;
    const float* Wp = W + (size_t)(bn + grow) * DM + gc4 * 4;

    float c[2][8][4] = {};

    for (int k0 = 0; k0 < DM; k0 += 32) {
        float4 av[4], bv[4];
#pragma unroll
        for (int i = 0; i < 4; i++) {
            av[i] = *(const float4*)(Xp + k0 + (size_t)i * 32 * DM);
            bv[i] = *(const float4*)(Wp + k0 + (size_t)i * 32 * DM);
        }
        __syncthreads();
#pragma unroll
        for (int i = 0; i < 4; i++) {
            uint32_t byte = (uint32_t)(grow + 32 * i) * 80u + (uint32_t)gc4 * 8u;
            uint32_t h0, h1, l0, l1;
            split4(av[i], h0, h1, l0, l1);
            asm volatile("st.shared.v2.b32 [%0], {%1,%2};" :: "r"(uAhi + byte), "r"(h0), "r"(h1) : "memory");
            asm volatile("st.shared.v2.b32 [%0], {%1,%2};" :: "r"(uAlo + byte), "r"(l0), "r"(l1) : "memory");
            split4(bv[i], h0, h1, l0, l1);
            asm volatile("st.shared.v2.b32 [%0], {%1,%2};" :: "r"(uBhi + byte), "r"(h0), "r"(h1) : "memory");
            asm volatile("st.shared.v2.b32 [%0], {%1,%2};" :: "r"(uBlo + byte), "r"(l0), "r"(l1) : "memory");
        }
        __syncthreads();

#pragma unroll
        for (int ks = 0; ks < 2; ks++) {
            const uint32_t kbyte = (uint32_t)ks * 32u + mkb;
            uint32_t ah[2][4], al[2][4];
#pragma unroll
            for (int mt = 0; mt < 2; mt++) {
                uint32_t off = (uint32_t)(wm * 32 + mt * 16 + mrow) * 80u + kbyte;
                ldmatrix_x4(ah[mt], uAhi + off);
                ldmatrix_x4(al[mt], uAlo + off);
            }
#pragma unroll
            for (int np = 0; np < 4; np++) {
                uint32_t bh[4], bl[4];
                uint32_t off = (uint32_t)(wn * 64 + np * 16 + mrow) * 80u + kbyte;
                ldmatrix_x4(bh, uBhi + off);
                ldmatrix_x4(bl, uBlo + off);
#pragma unroll
                for (int mt = 0; mt < 2; mt++) {
                    float* c0 = c[mt][2 * np + 0];
                    float* c1 = c[mt][2 * np + 1];
                    mma16816(c0, ah[mt], bh[0], bh[2]);
                    mma16816(c1, ah[mt], bh[1], bh[3]);
                    mma16816(c0, ah[mt], bl[0], bl[2]);
                    mma16816(c1, ah[mt], bl[1], bl[3]);
                    mma16816(c0, al[mt], bh[0], bh[2]);
                    mma16816(c1, al[mt], bh[1], bh[3]);
                }
            }
        }
    }

    const int g = lane >> 2, tg = lane & 3;
#pragma unroll
    for (int mt = 0; mt < 2; mt++) {
#pragma unroll
        for (int j = 0; j < 8; j++) {
            int col = bn + wn * 64 + j * 8 + tg * 2;
            float bb0 = __ldg(bias + col), bb1 = __ldg(bias + col + 1);
            int r0 = bm + wm * 32 + mt * 16 + g;
            float2 v0 = {c[mt][j][0] + bb0, c[mt][j][1] + bb1};
            float2 v1 = {c[mt][j][2] + bb0, c[mt][j][3] + bb1};
            if (MODE == 0) {
                size_t basep = ((size_t)((col >> 6) * T_SEQ)) * HD + (col & 63);
                *(float2*)(out + basep + (size_t)r0 * HD) = v0;
                *(float2*)(out + basep + (size_t)(r0 + 8) * HD) = v1;
            } else {
                *(float2*)(out + (size_t)r0 * DM + col) = v0;
                *(float2*)(out + (size_t)(r0 + 8) * DM + col) = v1;
            }
        }
    }
}

__global__ void __launch_bounds__(256, 2) gemm_mma_proj(const float* __restrict__ X,
                                                        const float* __restrict__ W,
                                                        const float* __restrict__ bias,
                                                        int which) {
    float* out = (which == 0) ? g_qh : (which == 1) ? g_kh : g_vh;
    gemm_mma_body<0>(X, W, bias, out);
}

__global__ void __launch_bounds__(256, 2) gemm_mma_out(const float* __restrict__ W,
                                                       const float* __restrict__ bias,
                                                       float* __restrict__ out) {
    gemm_mma_body<1>(g_ao, W, bias, out);
}

// ===========================================================================
// HMMA flash attention (causal). Block = (64-query tile, head), 4 warps.
// Warp w owns query rows 16w..16w+15. 3-term bf16 split on both GEMMs.
// FIX vs R5: row stride 72 bf16 (144 B) — rows hold HD=64 bf16 (128 B), the
// old 80 B stride overflowed. 144 % 128 == 16 keeps ldmatrix conflict-free.
// Q is staged through the K buffers (registers hold Q before K overwrites).
// ===========================================================================
#define AST 72   // attention smem row stride in bf16 elements (144 bytes)

__global__ void __launch_bounds__(128) flash_attn_mma() {
    __shared__ __nv_bfloat16 sKhi[64 * AST];
    __shared__ __nv_bfloat16 sKlo[64 * AST];
    __shared__ __nv_bfloat16 sVhi[64 * AST];
    __shared__ __nv_bfloat16 sVlo[64 * AST];

    const int tid = threadIdx.x;
    const int w = tid >> 5, lane = tid & 31;
    const int g = lane >> 2, tg = lane & 3;
    const uint32_t mrow = lane & 15;
    const uint32_t mkb = (lane >> 4) * 16;
    const int qt = blockIdx.x, h = blockIdx.y;
    const int q0 = qt * 64;

    const uint32_t uKhi = smem_to_u32(sKhi), uKlo = smem_to_u32(sKlo);
    const uint32_t uVhi = smem_to_u32(sVhi), uVlo = smem_to_u32(sVlo);

    // global loader mapping: 64x64 floats per tile, 128 threads, 8 float4 each
    const int grow0 = tid >> 4;          // 0..7 (+8 per i)
    const int gc4 = tid & 15;            // float4 col (0..15)
    const uint32_t sbyte0 = (uint32_t)grow0 * (AST * 2u) + (uint32_t)gc4 * 8u;

    // ---- stage Q through K buffers, split, hoist fragments to registers ----
    {
        const float* Qg = g_qh + ((size_t)h * T_SEQ + q0) * HD;
#pragma unroll
        for (int i = 0; i < 8; i++) {
            float4 v = *(const float4*)(Qg + (size_t)(grow0 + 8 * i) * HD + gc4 * 4);
            uint32_t h0, h1, l0, l1;
            split4(v, h0, h1, l0, l1);
            uint32_t byte = sbyte0 + (uint32_t)i * 8u * (AST * 2u);
            asm volatile("st.shared.v2.b32 [%0], {%1,%2};" :: "r"(uKhi + byte), "r"(h0), "r"(h1) : "memory");
            asm volatile("st.shared.v2.b32 [%0], {%1,%2};" :: "r"(uKlo + byte), "r"(l0), "r"(l1) : "memory");
        }
    }
    __syncthreads();

    uint32_t qh[4][4], ql[4][4];
#pragma unroll
    for (int kc = 0; kc < 4; kc++) {
        uint32_t off = (uint32_t)(w * 16 + mrow) * (AST * 2u) + (uint32_t)kc * 32u + mkb;
        ldmatrix_x4(qh[kc], uKhi + off);
        ldmatrix_x4(ql[kc], uKlo + off);
    }

    float O[8][4] = {};
    float m0 = -1e30f, m1 = -1e30f, l0s = 0.f, l1s = 0.f;

    for (int kt = 0; kt <= qt; kt++) {
        __syncthreads();   // prior tile's (or Q hoist's) smem reads done
        {
            const float* Kg = g_kh + ((size_t)h * T_SEQ + kt * 64) * HD;
            const float* Vg = g_vh + ((size_t)h * T_SEQ + kt * 64) * HD;
#pragma unroll
            for (int i = 0; i < 8; i++) {
                uint32_t byte = sbyte0 + (uint32_t)i * 8u * (AST * 2u);
                float4 kv = *(const float4*)(Kg + (size_t)(grow0 + 8 * i) * HD + gc4 * 4);
                uint32_t h0, h1, l0, l1;
                split4(kv, h0, h1, l0, l1);
                asm volatile("st.shared.v2.b32 [%0], {%1,%2};" :: "r"(uKhi + byte), "r"(h0), "r"(h1) : "memory");
                asm volatile("st.shared.v2.b32 [%0], {%1,%2};" :: "r"(uKlo + byte), "r"(l0), "r"(l1) : "memory");
                float4 vv = *(const float4*)(Vg + (size_t)(grow0 + 8 * i) * HD + gc4 * 4);
                split4(vv, h0, h1, l0, l1);
                asm volatile("st.shared.v2.b32 [%0], {%1,%2};" :: "r"(uVhi + byte), "r"(h0), "r"(h1) : "memory");
                asm volatile("st.shared.v2.b32 [%0], {%1,%2};" :: "r"(uVlo + byte), "r"(l0), "r"(l1) : "memory");
            }
        }
        __syncthreads();

        // ---- S = Q @ K^T (c[j] = 8-col key tile j) ----
        float c[8][4] = {};
#pragma unroll
        for (int kc = 0; kc < 4; kc++) {
#pragma unroll
            for (int np = 0; np < 4; np++) {
                uint32_t kh[4], kl[4];
                uint32_t off = (uint32_t)(np * 16 + mrow) * (AST * 2u) + (uint32_t)kc * 32u + mkb;
                ldmatrix_x4(kh, uKhi + off);
                ldmatrix_x4(kl, uKlo + off);
                float* c0 = c[2 * np + 0];
                float* c1 = c[2 * np + 1];
                mma16816(c0, qh[kc], kh[0], kh[2]);
                mma16816(c1, qh[kc], kh[1], kh[3]);
                mma16816(c0, qh[kc], kl[0], kl[2]);
                mma16816(c1, qh[kc], kl[1], kl[3]);
                mma16816(c0, ql[kc], kh[0], kh[2]);
                mma16816(c1, ql[kc], kh[1], kh[3]);
            }
        }

        // ---- scale + causal mask (diag tile only) ----
        const float scale = 0.125f;
        if (kt == qt) {
            const int r0 = 16 * w + g, r1 = r0 + 8;
#pragma unroll
            for (int j = 0; j < 8; j++) {
                int col = 8 * j + 2 * tg;
                c[j][0] = (col     <= r0) ? c[j][0] * scale : -1e30f;
                c[j][1] = (col + 1 <= r0) ? c[j][1] * scale : -1e30f;
                c[j][2] = (col     <= r1) ? c[j][2] * scale : -1e30f;
                c[j][3] = (col + 1 <= r1) ? c[j][3] * scale : -1e30f;
            }
        } else {
#pragma unroll
            for (int j = 0; j < 8; j++)
#pragma unroll
                for (int q = 0; q < 4; q++) c[j][q] *= scale;
        }

        // ---- online softmax (rows g and g+8; reduce over 4-lane group) ----
        float rm0 = -1e30f, rm1 = -1e30f;
#pragma unroll
        for (int j = 0; j < 8; j++) {
            rm0 = fmaxf(rm0, fmaxf(c[j][0], c[j][1]));
            rm1 = fmaxf(rm1, fmaxf(c[j][2], c[j][3]));
        }
        rm0 = fmaxf(rm0, __shfl_xor_sync(0xffffffffu, rm0, 1));
        rm0 = fmaxf(rm0, __shfl_xor_sync(0xffffffffu, rm0, 2));
        rm1 = fmaxf(rm1, __shfl_xor_sync(0xffffffffu, rm1, 1));
        rm1 = fmaxf(rm1, __shfl_xor_sync(0xffffffffu, rm1, 2));

        float mn0 = fmaxf(m0, rm0), mn1 = fmaxf(m1, rm1);
        float a0 = __expf(m0 - mn0), a1 = __expf(m1 - mn1);
        m0 = mn0; m1 = mn1;

        float rs0 = 0.f, rs1 = 0.f;
#pragma unroll
        for (int j = 0; j < 8; j++) {
            c[j][0] = __expf(c[j][0] - mn0);
            c[j][1] = __expf(c[j][1] - mn0);
            c[j][2] = __expf(c[j][2] - mn1);
            c[j][3] = __expf(c[j][3] - mn1);
            rs0 += c[j][0] + c[j][1];
            rs1 += c[j][2] + c[j][3];
        }
        rs0 += __shfl_xor_sync(0xffffffffu, rs0, 1);
        rs0 += __shfl_xor_sync(0xffffffffu, rs0, 2);
        rs1 += __shfl_xor_sync(0xffffffffu, rs1, 1);
        rs1 += __shfl_xor_sync(0xffffffffu, rs1, 2);
        l0s = l0s * a0 + rs0;
        l1s = l1s * a1 + rs1;
#pragma unroll
        for (int j = 0; j < 8; j++) {
            O[j][0] *= a0; O[j][1] *= a0;
            O[j][2] *= a1; O[j][3] *= a1;
        }

        // ---- O += P @ V  (P fragments straight from c; V via ldmatrix.trans)
#pragma unroll
        for (int kc = 0; kc < 4; kc++) {
            const int j0 = 2 * kc, j1 = 2 * kc + 1;
            uint32_t ph[4], pl[4];
            ph[0] = packbf2(c[j0][0], c[j0][1]);
            ph[1] = packbf2(c[j0][2], c[j0][3]);
            ph[2] = packbf2(c[j1][0], c[j1][1]);
            ph[3] = packbf2(c[j1][2], c[j1][3]);
            {
                __nv_bfloat162* H;
                H = (__nv_bfloat162*)&ph[0];
                pl[0] = packbf2(c[j0][0] - __bfloat162float(H->x), c[j0][1] - __bfloat162float(H->y));
                H = (__nv_bfloat162*)&ph[1];
                pl[1] = packbf2(c[j0][2] - __bfloat162float(H->x), c[j0][3] - __bfloat162float(H->y));
                H = (__nv_bfloat162*)&ph[2];
                pl[2] = packbf2(c[j1][0] - __bfloat162float(H->x), c[j1][1] - __bfloat162float(H->y));
                H = (__nv_bfloat162*)&ph[3];
                pl[3] = packbf2(c[j1][2] - __bfloat162float(H->x), c[j1][3] - __bfloat162float(H->y));
            }
#pragma unroll
            for (int dt = 0; dt < 4; dt++) {
                uint32_t vh[4], vl[4];
                uint32_t off = (uint32_t)(kc * 16 + mrow) * (AST * 2u) + (uint32_t)dt * 32u + mkb;
                ldmatrix_x4_trans(vh, uVhi + off);
                ldmatrix_x4_trans(vl, uVlo + off);
                float* o0 = O[2 * dt + 0];
                float* o1 = O[2 * dt + 1];
                mma16816(o0, ph, vh[0], vh[1]);
                mma16816(o1, ph, vh[2], vh[3]);
                mma16816(o0, ph, vl[0], vl[1]);
                mma16816(o1, ph, vl[2], vl[3]);
                mma16816(o0, pl, vh[0], vh[1]);
                mma16816(o1, pl, vh[2], vh[3]);
            }
        }
    }

    // ---- epilogue: O / l -> g_ao[t][h*64 + d] ----
    const float inv0 = 1.0f / l0s, inv1 = 1.0f / l1s;
    const int r0 = q0 + 16 * w + g, r1 = r0 + 8;
#pragma unroll
    for (int j = 0; j < 8; j++) {
        int d = 8 * j + 2 * tg;
        float2 v0 = {O[j][0] * inv0, O[j][1] * inv0};
        float2 v1 = {O[j][2] * inv1, O[j][3] * inv1};
        *(float2*)(g_ao + (size_t)r0 * DM + h * HD + d) = v0;
        *(float2*)(g_ao + (size_t)r1 * DM + h * HD + d) = v1;
    }
}

// ---------------------------------------------------------------------------
extern "C" void kernel_launch(void* const* d_in, const int* in_sizes, int n_in,
                              void* d_out, int out_size) {
    const float* q   = (const float*)d_in[0];
    const float* k   = (const float*)d_in[1];
    const float* v   = (const float*)d_in[2];
    // d_in[3] = causal mask (bool) — implied by causal structure, unused
    const float* w_q = (const float*)d_in[4];
    const float* b_q = (const float*)d_in[5];
    const float* w_k = (const float*)d_in[6];
    const float* b_k = (const float*)d_in[7];
    const float* w_v = (const float*)d_in[8];
    const float* b_v = (const float*)d_in[9];
    const float* w_o = (const float*)d_in[10];
    const float* b_o = (const float*)d_in[11];
    float* out = (float*)d_out;

    dim3 gg(DM / 128, T_SEQ / 128);   // (8, 32)
    gemm_mma_proj<<<gg, 256>>>(q, w_q, b_q, 0);
    gemm_mma_proj<<<gg, 256>>>(k, w_k, b_k, 1);
    gemm_mma_proj<<<gg, 256>>>(v, w_v, b_v, 2);
    flash_attn_mma<<<dim3(T_SEQ / 64, NH), 128>>>();
    gemm_mma_out<<<gg, 256>>>(w_o, b_o, out);
}